// round 16
// baseline (speedup 1.0000x reference)
#include <cuda_runtime.h>
#include <cuda_bf16.h>
#include <math.h>
#include <stdint.h>

// tcgen05 only exists in the arch-specific (sm_103a) device pass.
#if defined(__CUDA_ARCH_FEAT_SM103_ALL) || \
    (defined(__CUDA_ARCH_SPECIFIC__) && (__CUDA_ARCH__ == 1030))
#define HAS_TC 1
#else
#define HAS_TC 0
#endif

// ---------------- problem constants (fixed by the dataset) ----------------
#define N0C 50000
#define N1C 200000   // also max rows per level -> used as per-head stride
#define N2C 100000
#define FINC 500
#define DC 64

// ---------------- device scratch (no allocations allowed) ----------------
__device__ unsigned g_bits[N0C * 16];          // bit-packed binarized X0 (512 bits/node)
__device__ __align__(16) unsigned char g_Wt[3 * 2 * 8 * 16384]; // [lev][split][chunk] 128x64 bf16 SW128
__device__ float    g_Wp[3 * 512 * 128];       // fp32 packed weights (SIMT fallback)
__device__ float    g_bp[3 * 128];             // per-level packed bias
__device__ __align__(16) float g_Xh0[(size_t)N0C * 128];
__device__ __align__(16) float g_Xh1[(size_t)N1C * 128];
__device__ __align__(16) float g_Xh2[(size_t)N2C * 128];
__device__ float    g_p2[6 * N1C];             // exp(s2) per node per head
__device__ float    g_z [6 * N1C];             // softmax denominators
__device__ __align__(16) float g_H0[(size_t)N0C * 64];
__device__ __align__(16) float g_H1[(size_t)N1C * 64];
__device__ __align__(16) float g_H2[(size_t)N2C * 64];
__device__ __align__(16) float g_S1[(size_t)N0C * 64];   // spmm(B1, prelu(H1))
__device__ __align__(16) float g_U [(size_t)N1C * 64];   // spmm(B2, prelu(H2))
__device__ __align__(16) float g_V [(size_t)N0C * 64];   // spmm(B1, U)
__device__ float    g_tsum[N0C];               // rowsum of B1 values

// ---------------- PTX helpers (sm_103a-only emission) ----------------
__device__ __forceinline__ uint32_t smem_u32(const void* p) {
    uint32_t a;
    asm("{ .reg .u64 t; cvta.to.shared.u64 t, %1; cvt.u32.u64 %0, t; }" : "=r"(a) : "l"(p));
    return a;
}
#if HAS_TC
__device__ __forceinline__ uint32_t elect_one() {
    uint32_t pred;
    asm volatile("{\n\t.reg .pred p;\n\telect.sync _|p, 0xFFFFFFFF;\n\tselp.b32 %0, 1, 0, p;\n\t}" : "=r"(pred));
    return pred;
}
#define MBAR_INIT(addr, cnt) \
    asm volatile("mbarrier.init.shared.b64 [%0], %1;" :: "r"((uint32_t)(addr)), "r"((uint32_t)(cnt)) : "memory")
#define MBAR_WAIT(addr, par) do { \
    uint32_t _m = (uint32_t)(addr); uint32_t _p = (uint32_t)(par); uint32_t _d; \
    asm volatile("{\n\t.reg .pred p;\n\tmbarrier.try_wait.parity.acquire.cta.shared::cta.b64 p, [%1], %2;\n\tselp.b32 %0, 1, 0, p;\n\t}" \
        : "=r"(_d) : "r"(_m), "r"(_p) : "memory"); \
    if (!_d) { \
        asm volatile("{\n\t.reg .pred P1;\n\tWL_%=:\n\tmbarrier.try_wait.parity.acquire.cta.shared::cta.b64 P1, [%0], %1, 0x989680;\n\t@P1 bra.uni WD_%=;\n\tbra.uni WL_%=;\n\tWD_%=:\n\t}" \
            :: "r"(_m), "r"(_p) : "memory"); \
    } } while (0)
#define TC_ALLOC(sa, n)   asm volatile("tcgen05.alloc.cta_group::1.sync.aligned.shared::cta.b32 [%0], %1;" :: "r"((uint32_t)(sa)), "r"((uint32_t)(n)) : "memory")
#define TC_DEALLOC(t, n)  asm volatile("tcgen05.dealloc.cta_group::1.sync.aligned.b32 %0, %1;" :: "r"(t), "r"((uint32_t)(n)))
#define TC_COMMIT(mb)     asm volatile("tcgen05.commit.cta_group::1.mbarrier::arrive::one.shared::cluster.b64 [%0];" :: "r"((uint32_t)(mb)) : "memory")
#define TC_FENCE_AFTER()  asm volatile("tcgen05.fence::after_thread_sync;" ::: "memory")
#define TC_FENCE_BEFORE() asm volatile("tcgen05.fence::before_thread_sync;" ::: "memory")
#define TC_WAIT_LD()      asm volatile("tcgen05.wait::ld.sync.aligned;" ::: "memory")
#define FENCE_ASYNC()     asm volatile("fence.proxy.async.shared::cta;" ::: "memory")
#define TC_LD_X32(r, ta) \
    asm volatile("tcgen05.ld.sync.aligned.32x32b.x32.b32 " \
        "{%0, %1, %2, %3, %4, %5, %6, %7, %8, %9, %10, %11, %12, %13, %14, %15, " \
        " %16, %17, %18, %19, %20, %21, %22, %23, %24, %25, %26, %27, %28, %29, %30, %31}, [%32];" \
        : "=r"((r)[0]),  "=r"((r)[1]),  "=r"((r)[2]),  "=r"((r)[3]), \
          "=r"((r)[4]),  "=r"((r)[5]),  "=r"((r)[6]),  "=r"((r)[7]), \
          "=r"((r)[8]),  "=r"((r)[9]),  "=r"((r)[10]), "=r"((r)[11]), \
          "=r"((r)[12]), "=r"((r)[13]), "=r"((r)[14]), "=r"((r)[15]), \
          "=r"((r)[16]), "=r"((r)[17]), "=r"((r)[18]), "=r"((r)[19]), \
          "=r"((r)[20]), "=r"((r)[21]), "=r"((r)[22]), "=r"((r)[23]), \
          "=r"((r)[24]), "=r"((r)[25]), "=r"((r)[26]), "=r"((r)[27]), \
          "=r"((r)[28]), "=r"((r)[29]), "=r"((r)[30]), "=r"((r)[31]) \
        : "r"(ta))

static constexpr uint64_t DESC_BASE_SW128 =
    (uint64_t(2) << 61) | (uint64_t(1) << 46) | (uint64_t(64) << 32) | (uint64_t(1) << 16);
#define MAKE_DESC(a) (DESC_BASE_SW128 | ((uint64_t)((a) >> 4) & 0x3FFF))

#define MMA_IDESC_N64 ((1u << 4) | (1u << 7) | (1u << 10) | ((64u / 8u) << 17) | ((128u / 16u) << 24))

__device__ __forceinline__ void mma_f16_ss(uint32_t d, uint64_t a, uint64_t b, bool en) {
    uint32_t e = en ? 1u : 0u;
    asm volatile(
        "{\n\t.reg .pred p;\n\tsetp.ne.u32 p, %5, 0;\n\t"
        "tcgen05.mma.cta_group::1.kind::f16 [%0], %1, %2, %3, {%4, %4, %4, %4}, p;\n\t}"
        :: "r"(d), "l"(a), "l"(b), "r"(MMA_IDESC_N64), "r"(0u), "r"(e)
        : "memory");
}
#endif  // HAS_TC

// ---------------- 1) binarize + bitpack X0 ----------------
__global__ void pack_bits_kernel(const float* __restrict__ X0, int n0) {
    int lane = threadIdx.x & 31;
    int node = (blockIdx.x * blockDim.x + threadIdx.x) >> 5;
    if (node >= n0) return;
    const float* row = X0 + (size_t)node * FINC;
#pragma unroll
    for (int wd = 0; wd < 16; wd++) {
        int bi = wd * 32 + lane;
        float f = (bi < FINC) ? row[bi] : 0.f;
        unsigned m = __ballot_sync(0xffffffffu, f != 0.f);
        if (lane == 0) g_bits[node * 16 + wd] = m;
    }
}

// ---------------- 2a) pack W into hi/lo bf16 SW128 tiles + bias -----------
__global__ void pack_Wt_kernel(const float* __restrict__ W, const float* __restrict__ b) {
    int idx = blockIdx.x * blockDim.x + threadIdx.x;
    if (idx >= 3 * 8 * 128 * 64) return;
    int kk = idx & 63;
    int n = (idx >> 6) & 127;
    int chunk = (idx >> 13) & 7;
    int lev = idx >> 16;
    int head = lev * 2 + (n >> 6);
    int jj = n & 63;
    int k = chunk * 64 + kk;
    float w = (k < FINC) ? W[((size_t)head * FINC + k) * DC + jj] : 0.f;
    __nv_bfloat16 hi = __float2bfloat16(w);
    __nv_bfloat16 lo = __float2bfloat16(w - __bfloat162float(hi));
    unsigned off = n * 128 + kk * 2;
    unsigned sw = off ^ ((off >> 3) & 0x70);
    size_t base_hi = (((size_t)lev * 2 + 0) * 8 + chunk) * 16384;
    size_t base_lo = (((size_t)lev * 2 + 1) * 8 + chunk) * 16384;
    *(__nv_bfloat16*)(g_Wt + base_hi + sw) = hi;
    *(__nv_bfloat16*)(g_Wt + base_lo + sw) = lo;
    if (k == 0) g_bp[lev * 128 + n] = b[head * DC + jj];
}

// ---------------- 2b) pack W fp32 [512 x 128] per level (fallback) --------
__global__ void pack_W_kernel(const float* __restrict__ W) {
    int idx = blockIdx.x * blockDim.x + threadIdx.x;
    if (idx >= 3 * 512 * 128) return;
    int lev = idx / (512 * 128);
    int rem = idx - lev * (512 * 128);
    int k = rem >> 7;
    int j = rem & 127;
    int head = lev * 2 + (j >> 6);
    int jj = j & 63;
    g_Wp[idx] = (k < FINC) ? W[((size_t)head * FINC + k) * DC + jj] : 0.f;
}

// ---------------- 3) feature GEMM + fused p2 epilogue (R9/R11 config) ------
#define MTILES  4
#define SM_A    0
#define SM_B    65536
#define SM_BITS 98304
#define SM_IDS  131072
#define SM_BIAS 137216
#define SM_A2W  137728
#define SM_A2B  138240
#define SM_LUT  138256
#define SM_PTR  138384
#define SM_MBAR 138392
#define SMEM_TOTAL 138496
#define TMEM_COLS 512

__global__ void __launch_bounds__(256) __cluster_dims__(1, 1, 1)
mma_feat_kernel(int lev, int mode, int n, const int* __restrict__ elem,
                float* __restrict__ out,
                const float* __restrict__ a2w, const float* __restrict__ a2b) {
    extern __shared__ char smem[];
    int t = threadIdx.x;
    int tile0 = blockIdx.x * (128 * MTILES);

    {
        int* ids = (int*)(smem + SM_IDS);
        for (int i = t; i < 128 * MTILES; i += 256) {
            int gr = tile0 + i; if (gr >= n) gr = n - 1;
            int a, bb, c;
            if (mode == 0)      { a = gr; bb = gr; c = gr; }
            else if (mode == 1) { a = elem[2 * gr]; bb = elem[2 * gr + 1]; c = a; }
            else                { a = elem[3 * gr]; bb = elem[3 * gr + 1]; c = elem[3 * gr + 2]; }
            ids[i * 3] = a; ids[i * 3 + 1] = bb; ids[i * 3 + 2] = c;
        }
    }
    if (t < 128) {
        ((float*)(smem + SM_BIAS))[t] = g_bp[lev * 128 + t];
        ((float*)(smem + SM_A2W))[t] = a2w[(lev * 2 + (t >> 6)) * 64 + (t & 63)];
    }
    if (t < 2) ((float*)(smem + SM_A2B))[t] = a2b[lev * 2 + t];
    __syncthreads();
    {
        const int* ids = (const int*)(smem + SM_IDS);
        unsigned* sbits = (unsigned*)(smem + SM_BITS);
        for (int i = t; i < 128 * MTILES * 16; i += 256) {
            int row = i >> 4, w = i & 15;
            unsigned v = g_bits[ids[row * 3] * 16 + w];
            if (mode >= 1) v &= g_bits[ids[row * 3 + 1] * 16 + w];
            if (mode == 2) v &= g_bits[ids[row * 3 + 2] * 16 + w];
            sbits[i] = v;
        }
    }

#if HAS_TC
    uint32_t sb = smem_u32(smem);
    int wid = t >> 5;
    int lane = t & 31;
    if (wid == 0) {
        TC_ALLOC(sb + SM_PTR, TMEM_COLS);
    }
    if (t == 0) MBAR_INIT(sb + SM_MBAR, 1);
    if (t < 16) {
        unsigned w0 = ((t & 1) ? 0x3f80u : 0u) | ((t & 2) ? 0x3f800000u : 0u);
        unsigned w1 = ((t & 4) ? 0x3f80u : 0u) | ((t & 8) ? 0x3f800000u : 0u);
        ((uint2*)(smem + SM_LUT))[t] = make_uint2(w0, w1);
    }
    __syncthreads();

    uint32_t tmem;
    asm volatile("ld.shared.b32 %0, [%1];" : "=r"(tmem) : "r"(sb + SM_PTR));

    const uint2* lut = (const uint2*)(smem + SM_LUT);
    const unsigned* sbits = (const unsigned*)(smem + SM_BITS);
    int arow = t >> 1, ahalf = t & 1;
    const unsigned char* wt = g_Wt + (size_t)lev * (2 * 8 * 16384);

    for (int c = 0; c < 8; c++) {
#pragma unroll
        for (int tile = 0; tile < MTILES; tile++) {
            unsigned bw = sbits[(tile * 128 + arow) * 16 + 2 * c + ahalf];
            char* Abuf = smem + SM_A + tile * 16384;
#pragma unroll
            for (int j = 0; j < 4; j++) {
                unsigned nib0 = (bw >> (j * 8)) & 15u;
                unsigned nib1 = (bw >> (j * 8 + 4)) & 15u;
                uint2 p0 = lut[nib0];
                uint2 p1 = lut[nib1];
                unsigned off = arow * 128 + ahalf * 64 + j * 16;
                unsigned sw = off ^ ((off >> 3) & 0x70);
                *(uint4*)(Abuf + sw) = make_uint4(p0.x, p0.y, p1.x, p1.y);
            }
        }
        {
            const uint4* srcHi = (const uint4*)(wt + (size_t)c * 16384);
            const uint4* srcLo = (const uint4*)(wt + (size_t)(8 + c) * 16384);
            uint4* dstB = (uint4*)(smem + SM_B);
#pragma unroll
            for (int q = 0; q < 4; q++) dstB[q * 256 + t] = srcHi[q * 256 + t];
#pragma unroll
            for (int q = 0; q < 4; q++) dstB[1024 + q * 256 + t] = srcLo[q * 256 + t];
        }
        FENCE_ASYNC();
        __syncthreads();

        if (wid == 0 && elect_one()) {
            uint64_t bdescH = MAKE_DESC(sb + SM_B);
            uint64_t bdescL = MAKE_DESC(sb + SM_B + 16384);
#pragma unroll
            for (int tile = 0; tile < MTILES; tile++) {
                uint64_t adesc = MAKE_DESC(sb + SM_A + tile * 16384);
                uint32_t dbase = tmem + tile * 128;
#pragma unroll
                for (int ks = 0; ks < 4; ks++) {
                    bool first = (c == 0 && ks == 0);
#pragma unroll
                    for (int h = 0; h < 2; h++) {
                        mma_f16_ss(dbase + h * 64, adesc + ks * 2,
                                   bdescH + h * 512 + ks * 2, !first);
                        mma_f16_ss(dbase + h * 64, adesc + ks * 2,
                                   bdescL + h * 512 + ks * 2, true);
                    }
                }
            }
            TC_COMMIT(sb + SM_MBAR);
        }
        MBAR_WAIT(sb + SM_MBAR, c & 1);
        __syncthreads();
    }

    TC_FENCE_AFTER();

    {
        int part = wid & 3, colg = wid >> 2;
        const float* bias = (const float*)(smem + SM_BIAS) + colg * 64;
        const float* sa2w = (const float*)(smem + SM_A2W) + colg * 64;
        float a2bv = ((const float*)(smem + SM_A2B))[colg];
#pragma unroll
        for (int tile = 0; tile < MTILES; tile++) {
            uint32_t d0[32], d1[32];
            TC_LD_X32(d0, tmem + tile * 128 + colg * 64);
            TC_LD_X32(d1, tmem + tile * 128 + colg * 64 + 32);
            TC_WAIT_LD();
            TC_FENCE_BEFORE();
            int gr = tile0 + tile * 128 + part * 32 + lane;
            if (gr < n) {
                float* o = out + (size_t)gr * 128 + colg * 64;
                float s2 = 0.f;
#pragma unroll
                for (int j = 0; j < 8; j++) {
                    float4 v;
                    v.x = __uint_as_float(d0[j * 4 + 0]) + bias[j * 4 + 0];
                    v.y = __uint_as_float(d0[j * 4 + 1]) + bias[j * 4 + 1];
                    v.z = __uint_as_float(d0[j * 4 + 2]) + bias[j * 4 + 2];
                    v.w = __uint_as_float(d0[j * 4 + 3]) + bias[j * 4 + 3];
                    s2 = fmaf(v.x, sa2w[j * 4 + 0], s2);
                    s2 = fmaf(v.y, sa2w[j * 4 + 1], s2);
                    s2 = fmaf(v.z, sa2w[j * 4 + 2], s2);
                    s2 = fmaf(v.w, sa2w[j * 4 + 3], s2);
                    *(float4*)(o + j * 4) = v;
                }
#pragma unroll
                for (int j = 0; j < 8; j++) {
                    float4 v;
                    v.x = __uint_as_float(d1[j * 4 + 0]) + bias[32 + j * 4 + 0];
                    v.y = __uint_as_float(d1[j * 4 + 1]) + bias[32 + j * 4 + 1];
                    v.z = __uint_as_float(d1[j * 4 + 2]) + bias[32 + j * 4 + 2];
                    v.w = __uint_as_float(d1[j * 4 + 3]) + bias[32 + j * 4 + 3];
                    s2 = fmaf(v.x, sa2w[32 + j * 4 + 0], s2);
                    s2 = fmaf(v.y, sa2w[32 + j * 4 + 1], s2);
                    s2 = fmaf(v.z, sa2w[32 + j * 4 + 2], s2);
                    s2 = fmaf(v.w, sa2w[32 + j * 4 + 3], s2);
                    *(float4*)(o + 32 + j * 4) = v;
                }
                g_p2[(lev * 2 + colg) * N1C + gr] = expf(s2 + a2bv);
            }
        }
    }
    __syncthreads();
    if (wid == 0) TC_DEALLOC(tmem, TMEM_COLS);

#else  // ---------------- SIMT fallback (non-sm_103a pass; dead on GB300) --
    const float* Wp = g_Wp + (size_t)lev * 512 * 128;
    float* sW = (float*)(smem + SM_A);
    const unsigned* sbits = (const unsigned*)(smem + SM_BITS);
    int tr = t >> 4, tc = t & 15;
    for (int tile = 0; tile < MTILES; tile++) {
        for (int h = 0; h < 2; h++) {
            float acc[4][8];
#pragma unroll
            for (int i = 0; i < 4; i++)
#pragma unroll
                for (int c = 0; c < 8; c++) acc[i][c] = 0.f;
            for (int w = 0; w < 16; w++) {
                __syncthreads();
                const float4* src = (const float4*)(Wp + (size_t)w * 4096);
                float4* dst = (float4*)sW;
#pragma unroll
                for (int q = 0; q < 4; q++) dst[q * 256 + t] = src[q * 256 + t];
                __syncthreads();
                unsigned a[4];
#pragma unroll
                for (int i = 0; i < 4; i++)
                    a[i] = sbits[(tile * 128 + h * 64 + tr + i * 16) * 16 + w];
                const float4* sv = (const float4*)sW;
#pragma unroll
                for (int kk = 0; kk < 32; kk++) {
                    float4 w0 = sv[kk * 32 + tc * 2];
                    float4 w1 = sv[kk * 32 + tc * 2 + 1];
#pragma unroll
                    for (int i = 0; i < 4; i++) {
                        unsigned msk = (unsigned)(-(int)((a[i] >> kk) & 1u));
                        float av = __uint_as_float(0x3f800000u & msk);
                        acc[i][0] = fmaf(av, w0.x, acc[i][0]);
                        acc[i][1] = fmaf(av, w0.y, acc[i][1]);
                        acc[i][2] = fmaf(av, w0.z, acc[i][2]);
                        acc[i][3] = fmaf(av, w0.w, acc[i][3]);
                        acc[i][4] = fmaf(av, w1.x, acc[i][4]);
                        acc[i][5] = fmaf(av, w1.y, acc[i][5]);
                        acc[i][6] = fmaf(av, w1.z, acc[i][6]);
                        acc[i][7] = fmaf(av, w1.w, acc[i][7]);
                    }
                }
            }
            const float* bias = (const float*)(smem + SM_BIAS) + tc * 8;
#pragma unroll
            for (int i = 0; i < 4; i++) {
                int r = tile0 + tile * 128 + h * 64 + tr + i * 16;
                if (r < n) {
                    float* o = out + (size_t)r * 128 + tc * 8;
#pragma unroll
                    for (int c = 0; c < 8; c++) o[c] = acc[i][c] + bias[c];
                }
            }
        }
    }
#endif
}

// ---------------- 4) z pass: z[r] += p2[c] over COO rows -------------------
__global__ void z_kernel(const int* __restrict__ idx, int nnz, int hA, int hB) {
    int j = blockIdx.x * blockDim.x + threadIdx.x;
    if (j >= nnz) return;
    int r = idx[j], c = idx[nnz + j];
    atomicAdd(&g_z[hA * N1C + r], g_p2[hA * N1C + c]);
    if (hB >= 0) atomicAdd(&g_z[hB * N1C + r], g_p2[hB * N1C + c]);
}

// ---------------- 5) dual-head direct-normalized scatter (shared idx) ------
__global__ void att_scatter2_kernel(const int* __restrict__ idx, int nnz, int hA, int hB,
                                    const float* __restrict__ Xh, float* __restrict__ H) {
    int warp = (blockIdx.x * blockDim.x + threadIdx.x) >> 5;
    int lane = threadIdx.x & 31;
    int j = warp * 2 + (lane >> 4);
    int l = lane & 15;
    if (j >= nnz) return;
    int r = idx[j], c = idx[nnz + j];
    float wA = __fdividef(g_p2[hA * N1C + c], g_z[hA * N1C + r]);
    float wB = __fdividef(g_p2[hB * N1C + c], g_z[hB * N1C + r]);
    float4 hA4 = *(const float4*)(Xh + (size_t)c * 128 + l * 4);
    float4 hB4 = *(const float4*)(Xh + (size_t)c * 128 + 64 + l * 4);
    float4 v;
    v.x = wA * hA4.x + wB * hB4.x;
    v.y = wA * hA4.y + wB * hB4.y;
    v.z = wA * hA4.z + wB * hB4.z;
    v.w = wA * hA4.w + wB * hB4.w;
    atomicAdd((float4*)(H + (size_t)r * 64 + l * 4), v);
}

// ---------------- 6) single-head direct-normalized scatter -----------------
__global__ void att_scatter1_kernel(const int* __restrict__ idx, int nnz, int head,
                                    const float* __restrict__ Xh, float* __restrict__ H) {
    int warp = (blockIdx.x * blockDim.x + threadIdx.x) >> 5;
    int lane = threadIdx.x & 31;
    int j = warp * 2 + (lane >> 4);
    int l = lane & 15;
    if (j >= nnz) return;
    int r = idx[j], c = idx[nnz + j];
    float w = __fdividef(g_p2[head * N1C + c], g_z[head * N1C + r]);
    int hoff = (head & 1) * 64;
    float4 hv = *(const float4*)(Xh + (size_t)c * 128 + hoff + l * 4);
    float4 v; v.x = w * hv.x; v.y = w * hv.y; v.z = w * hv.z; v.w = w * hv.w;
    atomicAdd((float4*)(H + (size_t)r * 64 + l * 4), v);
}

// ---------------- 7) COO spmm with fused PReLU on src ----------------------
__global__ void spmm_kernel(const int* __restrict__ idx, const float* __restrict__ vals,
                            int nnz, const float* __restrict__ src, float* __restrict__ dst,
                            const float* __restrict__ pw) {
    int warp = (blockIdx.x * blockDim.x + threadIdx.x) >> 5;
    int lane = threadIdx.x & 31;
    int j = warp * 2 + (lane >> 4);
    int l = lane & 15;
    if (j >= nnz) return;
    int r = idx[j], c = idx[nnz + j];
    float val = vals[j];
    float p = pw[0];
    float4 x = *(const float4*)(src + (size_t)c * 64 + l * 4);
    x.x = (x.x >= 0.f) ? x.x : p * x.x;
    x.y = (x.y >= 0.f) ? x.y : p * x.y;
    x.z = (x.z >= 0.f) ? x.z : p * x.z;
    x.w = (x.w >= 0.f) ? x.w : p * x.w;
    float4 v; v.x = val * x.x; v.y = val * x.y; v.z = val * x.z; v.w = val * x.w;
    atomicAdd((float4*)(dst + (size_t)r * 64 + l * 4), v);
}

// ---------------- 7b) COO spmm without activation (V += val * U[c]) --------
__global__ void spmm_noact_kernel(const int* __restrict__ idx, const float* __restrict__ vals,
                                  int nnz, const float* __restrict__ src, float* __restrict__ dst) {
    int warp = (blockIdx.x * blockDim.x + threadIdx.x) >> 5;
    int lane = threadIdx.x & 31;
    int j = warp * 2 + (lane >> 4);
    int l = lane & 15;
    if (j >= nnz) return;
    int r = idx[j], c = idx[nnz + j];
    float val = vals[j];
    float4 x = *(const float4*)(src + (size_t)c * 64 + l * 4);
    float4 v; v.x = val * x.x; v.y = val * x.y; v.z = val * x.z; v.w = val * x.w;
    atomicAdd((float4*)(dst + (size_t)r * 64 + l * 4), v);
}

// ---------------- 7c) tsum: rowsum of B1 values (no computed inputs) -------
__global__ void tsum_kernel(const int* __restrict__ idx, const float* __restrict__ vals,
                            int nnz) {
    int j = blockIdx.x * blockDim.x + threadIdx.x;
    if (j >= nnz) return;
    atomicAdd(&g_tsum[idx[j]], vals[j]);
}

// ---------------- 8) final: out = (prelu(H0) + S1 + V@triW + tsum*trib)/3 --
__global__ void __launch_bounds__(256)
final_kernel(const float* __restrict__ triW, const float* __restrict__ trib,
             float* __restrict__ out, int n0, const float* __restrict__ pw) {
    __shared__ float sT[64 * 64];
    int t = threadIdx.x;
#pragma unroll
    for (int q = 0; q < 16; q++) sT[q * 256 + t] = triW[q * 256 + t];
    __syncthreads();
    int gw = blockIdx.x * 8 + (t >> 5);
    int lane = t & 31;
    if (gw >= n0) return;
    float p = pw[0];
    float2 v = *(const float2*)(g_V + (size_t)gw * 64 + lane * 2);
    float2 o; o.x = 0.f; o.y = 0.f;
#pragma unroll
    for (int k = 0; k < 64; k++) {
        float vk = __shfl_sync(0xffffffffu, (k & 1) ? v.y : v.x, k >> 1);
        float2 tw = *(const float2*)(sT + k * 64 + lane * 2);
        o.x = fmaf(vk, tw.x, o.x);
        o.y = fmaf(vk, tw.y, o.y);
    }
    float2 h0 = *(const float2*)(g_H0 + (size_t)gw * 64 + lane * 2);
    h0.x = (h0.x >= 0.f) ? h0.x : p * h0.x;
    h0.y = (h0.y >= 0.f) ? h0.y : p * h0.y;
    float2 s1 = *(const float2*)(g_S1 + (size_t)gw * 64 + lane * 2);
    float ts = g_tsum[gw];
    float2 tb = *(const float2*)(trib + lane * 2);
    float2 r;
    r.x = (h0.x + s1.x + o.x + ts * tb.x) * (1.f / 3.f);
    r.y = (h0.y + s1.y + o.y + ts * tb.y) * (1.f / 3.f);
    *(float2*)(out + (size_t)gw * 64 + lane * 2) = r;
}

// ======================== host launcher ====================================
static inline void* symaddr(const void* sym) {
    void* p = nullptr;
    cudaGetSymbolAddress(&p, sym);
    return p;
}

extern "C" void kernel_launch(void* const* d_in, const int* in_sizes, int n_in,
                              void* d_out, int out_size) {
    const float* X0  = (const float*)d_in[0];
    const int*   E1  = (const int*)d_in[1];
    const int*   T2  = (const int*)d_in[2];
    const int*   L0  = (const int*)d_in[3];
    const int*   L1a = (const int*)d_in[4];
    const int*   L1b = (const int*)d_in[5];
    const int*   L2  = (const int*)d_in[6];
    const int*   B1i = (const int*)d_in[7];
    const float* B1v = (const float*)d_in[8];
    const int*   B2i = (const int*)d_in[9];
    const float* B2v = (const float*)d_in[10];
    const float* W   = (const float*)d_in[11];
    const float* b   = (const float*)d_in[12];
    const float* a2w = (const float*)d_in[15];
    const float* a2b = (const float*)d_in[16];
    const float* pw  = (const float*)d_in[17];
    const float* triW = (const float*)d_in[18];
    const float* trib = (const float*)d_in[19];

    int n0 = in_sizes[0] / FINC;
    int n1 = in_sizes[1] / 2;
    int n2 = in_sizes[2] / 3;
    int nnz0  = in_sizes[3] / 2;
    int nnz1a = in_sizes[4] / 2;
    int nnz1b = in_sizes[5] / 2;
    int nnz2  = in_sizes[6] / 2;
    int nb1 = in_sizes[8];
    int nb2 = in_sizes[10];

    float* Xh0 = (float*)symaddr(g_Xh0);
    float* Xh1 = (float*)symaddr(g_Xh1);
    float* Xh2 = (float*)symaddr(g_Xh2);
    float* H0  = (float*)symaddr(g_H0);
    float* H1  = (float*)symaddr(g_H1);
    float* H2  = (float*)symaddr(g_H2);
    float* S1  = (float*)symaddr(g_S1);
    float* U   = (float*)symaddr(g_U);
    float* V   = (float*)symaddr(g_V);
    float* tsum = (float*)symaddr(g_tsum);
    float* z   = (float*)symaddr(g_z);

    // one-time setup (first call is the uncaptured correctness run)
    static cudaStream_t sA = nullptr, sB = nullptr, sC = nullptr;
    static cudaEvent_t evStart = nullptr, evFork = nullptr, evG1 = nullptr;
    static cudaEvent_t evA = nullptr, evB = nullptr, evC = nullptr;
    static bool init_done = false;
    if (!init_done) {
        cudaFuncSetAttribute(mma_feat_kernel,
                             cudaFuncAttributeMaxDynamicSharedMemorySize, SMEM_TOTAL);
        cudaStreamCreateWithFlags(&sA, cudaStreamNonBlocking);
        cudaStreamCreateWithFlags(&sB, cudaStreamNonBlocking);
        cudaStreamCreateWithFlags(&sC, cudaStreamNonBlocking);
        cudaEventCreateWithFlags(&evStart, cudaEventDisableTiming);
        cudaEventCreateWithFlags(&evFork, cudaEventDisableTiming);
        cudaEventCreateWithFlags(&evG1, cudaEventDisableTiming);
        cudaEventCreateWithFlags(&evA, cudaEventDisableTiming);
        cudaEventCreateWithFlags(&evB, cudaEventDisableTiming);
        cudaEventCreateWithFlags(&evC, cudaEventDisableTiming);
        init_done = true;
    }

    // ---- immediate fork so per-stream memsets overlap the packs ----
    cudaEventRecord(evStart, 0);
    cudaStreamWaitEvent(sB, evStart, 0);
    cudaStreamWaitEvent(sC, evStart, 0);
    cudaStreamWaitEvent(sA, evStart, 0);

    // per-stream buffer zeroing (off the pack critical path)
    // sB: level-1 buffers + S1 (S1-half-spmm runs on sB)
    cudaMemsetAsync(H1, 0, sizeof(float) * (size_t)n1 * 64, sB);
    cudaMemsetAsync(z + 2 * N1C, 0, sizeof(float) * 2 * N1C, sB);      // heads 2,3
    cudaMemsetAsync(S1, 0, sizeof(float) * (size_t)n0 * 64, sB);
    // sC: level-2 buffers + V (V-half-spmm runs on sC)
    cudaMemsetAsync(H2, 0, sizeof(float) * (size_t)n2 * 64, sC);
    cudaMemsetAsync(U,  0, sizeof(float) * (size_t)n1 * 64, sC);
    cudaMemsetAsync(z + 4 * N1C, 0, sizeof(float) * 2 * N1C, sC);      // heads 4,5
    cudaMemsetAsync(V,  0, sizeof(float) * (size_t)n0 * 64, sC);
    // sA: level-0 buffers + tsum (computed early: needs only B1 inputs)
    cudaMemsetAsync(H0, 0, sizeof(float) * (size_t)n0 * 64, sA);
    cudaMemsetAsync(z,  0, sizeof(float) * 2 * N1C, sA);               // heads 0,1
    cudaMemsetAsync(tsum, 0, sizeof(float) * (size_t)n0, sA);
    tsum_kernel<<<(nb1 + 255) / 256, 256, 0, sA>>>(B1i, B1v, nb1);
    pack_W_kernel<<<(3 * 512 * 128 + 255) / 256, 256, 0, sA>>>(W);     // fallback-only

    // ---- packs on the capture stream (GEMM prerequisites) ----
    pack_bits_kernel<<<(n0 * 32 + 255) / 256, 256>>>(X0, n0);
    pack_Wt_kernel<<<(3 * 8 * 128 * 64 + 255) / 256, 256>>>(W, b);
    cudaEventRecord(evFork, 0);
    cudaStreamWaitEvent(sB, evFork, 0);
    cudaStreamWaitEvent(sC, evFork, 0);
    cudaStreamWaitEvent(sA, evFork, 0);

    // level 1 (edges) FIRST on stream B: gates the longest chain
    mma_feat_kernel<<<(n1 + 511) / 512, 256, SMEM_TOTAL, sB>>>(1, 1, n1, E1, Xh1, a2w, a2b);
    cudaEventRecord(evG1, sB);
    z_kernel<<<(nnz1a + 255) / 256, 256, 0, sB>>>(L1a, nnz1a, 2, -1);
    att_scatter1_kernel<<<(nnz1a + 15) / 16, 256, 0, sB>>>(L1a, nnz1a, 2, Xh1, H1);

    // level 2 (triangles) on stream C, then B2-spmm (U), then V-half-spmm
    mma_feat_kernel<<<(n2 + 511) / 512, 256, SMEM_TOTAL, sC>>>(2, 2, n2, T2, Xh2, a2w, a2b);
    z_kernel<<<(nnz2 + 255) / 256, 256, 0, sC>>>(L2, nnz2, 4, 5);
    att_scatter2_kernel<<<(nnz2 + 15) / 16, 256, 0, sC>>>(L2, nnz2, 4, 5, Xh2, H2);
    spmm_kernel<<<(nb2 + 15) / 16, 256, 0, sC>>>(B2i, B2v, nb2, H2, U, pw);
    spmm_noact_kernel<<<(nb1 + 15) / 16, 256, 0, sC>>>(B1i, B1v, nb1, U, V);
    cudaEventRecord(evC, sC);

    // level 0 (nodes) on stream A, then the head-3 chain once GEMM1 is done
    mma_feat_kernel<<<(n0 + 511) / 512, 256, SMEM_TOTAL, sA>>>(0, 0, n0, E1, Xh0, a2w, a2b);
    z_kernel<<<(nnz0 + 255) / 256, 256, 0, sA>>>(L0, nnz0, 0, 1);
    att_scatter2_kernel<<<(nnz0 + 15) / 16, 256, 0, sA>>>(L0, nnz0, 0, 1, Xh0, H0);
    cudaStreamWaitEvent(sA, evG1, 0);
    z_kernel<<<(nnz1b + 255) / 256, 256, 0, sA>>>(L1b, nnz1b, 3, -1);
    att_scatter1_kernel<<<(nnz1b + 15) / 16, 256, 0, sA>>>(L1b, nnz1b, 3, Xh1, H1);
    cudaEventRecord(evA, sA);

    // S1-half-spmm on sB once H1 fully assembled (scatter1a on sB + scatter1b on sA)
    cudaStreamWaitEvent(sB, evA, 0);
    spmm_kernel<<<(nb1 + 15) / 16, 256, 0, sB>>>(B1i, B1v, nb1, H1, S1, pw);
    cudaEventRecord(evB, sB);

    // ---- join on the capture stream ----
    cudaStreamWaitEvent(0, evB, 0);
    cudaStreamWaitEvent(0, evC, 0);
    cudaStreamWaitEvent(0, evA, 0);

    // final combine (needs H0, S1, V, tsum)
    final_kernel<<<(n0 + 7) / 8, 256>>>(triW, trib, (float*)d_out, n0, pw);
}

// round 17
// speedup vs baseline: 1.0456x; 1.0456x over previous
#include <cuda_runtime.h>
#include <cuda_bf16.h>
#include <math.h>
#include <stdint.h>

// tcgen05 only exists in the arch-specific (sm_103a) device pass.
#if defined(__CUDA_ARCH_FEAT_SM103_ALL) || \
    (defined(__CUDA_ARCH_SPECIFIC__) && (__CUDA_ARCH__ == 1030))
#define HAS_TC 1
#else
#define HAS_TC 0
#endif

// ---------------- problem constants (fixed by the dataset) ----------------
#define N0C 50000
#define N1C 200000   // also max rows per level -> used as per-head stride
#define N2C 100000
#define FINC 500
#define DC 64

// ---------------- device scratch (no allocations allowed) ----------------
__device__ unsigned g_bits[N0C * 16];          // bit-packed binarized X0 (512 bits/node)
__device__ __align__(16) unsigned char g_Wt[3 * 2 * 8 * 16384]; // [lev][split][chunk] 128x64 bf16 SW128
__device__ float    g_Wp[3 * 512 * 128];       // fp32 packed weights (SIMT fallback)
__device__ float    g_bp[3 * 128];             // per-level packed bias
__device__ __align__(16) float g_Xh0[(size_t)N0C * 128];
__device__ __align__(16) float g_Xh1[(size_t)N1C * 128];
__device__ __align__(16) float g_Xh2[(size_t)N2C * 128];
__device__ float    g_p2[6 * N1C];             // exp(s2) per node per head
__device__ float    g_z [6 * N1C];             // softmax denominators
__device__ __align__(16) float g_H0[(size_t)N0C * 64];
__device__ __align__(16) float g_H1[(size_t)N1C * 64];
__device__ __align__(16) float g_H2[(size_t)N2C * 64];
__device__ __align__(16) float g_S1[(size_t)N0C * 64];   // spmm(B1, prelu(H1))
__device__ __align__(16) float g_U [(size_t)N1C * 64];   // spmm(B2, prelu(H2))
__device__ __align__(16) float g_V [(size_t)N0C * 64];   // spmm(B1, U)
__device__ float    g_tsum[N0C];               // rowsum of B1 values

// ---------------- PTX helpers (sm_103a-only emission) ----------------
__device__ __forceinline__ uint32_t smem_u32(const void* p) {
    uint32_t a;
    asm("{ .reg .u64 t; cvta.to.shared.u64 t, %1; cvt.u32.u64 %0, t; }" : "=r"(a) : "l"(p));
    return a;
}
#if HAS_TC
__device__ __forceinline__ uint32_t elect_one() {
    uint32_t pred;
    asm volatile("{\n\t.reg .pred p;\n\telect.sync _|p, 0xFFFFFFFF;\n\tselp.b32 %0, 1, 0, p;\n\t}" : "=r"(pred));
    return pred;
}
#define MBAR_INIT(addr, cnt) \
    asm volatile("mbarrier.init.shared.b64 [%0], %1;" :: "r"((uint32_t)(addr)), "r"((uint32_t)(cnt)) : "memory")
#define MBAR_WAIT(addr, par) do { \
    uint32_t _m = (uint32_t)(addr); uint32_t _p = (uint32_t)(par); uint32_t _d; \
    asm volatile("{\n\t.reg .pred p;\n\tmbarrier.try_wait.parity.acquire.cta.shared::cta.b64 p, [%1], %2;\n\tselp.b32 %0, 1, 0, p;\n\t}" \
        : "=r"(_d) : "r"(_m), "r"(_p) : "memory"); \
    if (!_d) { \
        asm volatile("{\n\t.reg .pred P1;\n\tWL_%=:\n\tmbarrier.try_wait.parity.acquire.cta.shared::cta.b64 P1, [%0], %1, 0x989680;\n\t@P1 bra.uni WD_%=;\n\tbra.uni WL_%=;\n\tWD_%=:\n\t}" \
            :: "r"(_m), "r"(_p) : "memory"); \
    } } while (0)
#define TC_ALLOC(sa, n)   asm volatile("tcgen05.alloc.cta_group::1.sync.aligned.shared::cta.b32 [%0], %1;" :: "r"((uint32_t)(sa)), "r"((uint32_t)(n)) : "memory")
#define TC_DEALLOC(t, n)  asm volatile("tcgen05.dealloc.cta_group::1.sync.aligned.b32 %0, %1;" :: "r"(t), "r"((uint32_t)(n)))
#define TC_COMMIT(mb)     asm volatile("tcgen05.commit.cta_group::1.mbarrier::arrive::one.shared::cluster.b64 [%0];" :: "r"((uint32_t)(mb)) : "memory")
#define TC_FENCE_AFTER()  asm volatile("tcgen05.fence::after_thread_sync;" ::: "memory")
#define TC_FENCE_BEFORE() asm volatile("tcgen05.fence::before_thread_sync;" ::: "memory")
#define TC_WAIT_LD()      asm volatile("tcgen05.wait::ld.sync.aligned;" ::: "memory")
#define FENCE_ASYNC()     asm volatile("fence.proxy.async.shared::cta;" ::: "memory")
#define TC_LD_X32(r, ta) \
    asm volatile("tcgen05.ld.sync.aligned.32x32b.x32.b32 " \
        "{%0, %1, %2, %3, %4, %5, %6, %7, %8, %9, %10, %11, %12, %13, %14, %15, " \
        " %16, %17, %18, %19, %20, %21, %22, %23, %24, %25, %26, %27, %28, %29, %30, %31}, [%32];" \
        : "=r"((r)[0]),  "=r"((r)[1]),  "=r"((r)[2]),  "=r"((r)[3]), \
          "=r"((r)[4]),  "=r"((r)[5]),  "=r"((r)[6]),  "=r"((r)[7]), \
          "=r"((r)[8]),  "=r"((r)[9]),  "=r"((r)[10]), "=r"((r)[11]), \
          "=r"((r)[12]), "=r"((r)[13]), "=r"((r)[14]), "=r"((r)[15]), \
          "=r"((r)[16]), "=r"((r)[17]), "=r"((r)[18]), "=r"((r)[19]), \
          "=r"((r)[20]), "=r"((r)[21]), "=r"((r)[22]), "=r"((r)[23]), \
          "=r"((r)[24]), "=r"((r)[25]), "=r"((r)[26]), "=r"((r)[27]), \
          "=r"((r)[28]), "=r"((r)[29]), "=r"((r)[30]), "=r"((r)[31]) \
        : "r"(ta))

static constexpr uint64_t DESC_BASE_SW128 =
    (uint64_t(2) << 61) | (uint64_t(1) << 46) | (uint64_t(64) << 32) | (uint64_t(1) << 16);
#define MAKE_DESC(a) (DESC_BASE_SW128 | ((uint64_t)((a) >> 4) & 0x3FFF))

#define MMA_IDESC_N64 ((1u << 4) | (1u << 7) | (1u << 10) | ((64u / 8u) << 17) | ((128u / 16u) << 24))

__device__ __forceinline__ void mma_f16_ss(uint32_t d, uint64_t a, uint64_t b, bool en) {
    uint32_t e = en ? 1u : 0u;
    asm volatile(
        "{\n\t.reg .pred p;\n\tsetp.ne.u32 p, %5, 0;\n\t"
        "tcgen05.mma.cta_group::1.kind::f16 [%0], %1, %2, %3, {%4, %4, %4, %4}, p;\n\t}"
        :: "r"(d), "l"(a), "l"(b), "r"(MMA_IDESC_N64), "r"(0u), "r"(e)
        : "memory");
}
#endif  // HAS_TC

// ---------------- 1) binarize + bitpack X0 ----------------
__global__ void pack_bits_kernel(const float* __restrict__ X0, int n0) {
    int lane = threadIdx.x & 31;
    int node = (blockIdx.x * blockDim.x + threadIdx.x) >> 5;
    if (node >= n0) return;
    const float* row = X0 + (size_t)node * FINC;
#pragma unroll
    for (int wd = 0; wd < 16; wd++) {
        int bi = wd * 32 + lane;
        float f = (bi < FINC) ? row[bi] : 0.f;
        unsigned m = __ballot_sync(0xffffffffu, f != 0.f);
        if (lane == 0) g_bits[node * 16 + wd] = m;
    }
}

// ---------------- 2a) pack W into hi/lo bf16 SW128 tiles + bias -----------
__global__ void pack_Wt_kernel(const float* __restrict__ W, const float* __restrict__ b) {
    int idx = blockIdx.x * blockDim.x + threadIdx.x;
    if (idx >= 3 * 8 * 128 * 64) return;
    int kk = idx & 63;
    int n = (idx >> 6) & 127;
    int chunk = (idx >> 13) & 7;
    int lev = idx >> 16;
    int head = lev * 2 + (n >> 6);
    int jj = n & 63;
    int k = chunk * 64 + kk;
    float w = (k < FINC) ? W[((size_t)head * FINC + k) * DC + jj] : 0.f;
    __nv_bfloat16 hi = __float2bfloat16(w);
    __nv_bfloat16 lo = __float2bfloat16(w - __bfloat162float(hi));
    unsigned off = n * 128 + kk * 2;
    unsigned sw = off ^ ((off >> 3) & 0x70);
    size_t base_hi = (((size_t)lev * 2 + 0) * 8 + chunk) * 16384;
    size_t base_lo = (((size_t)lev * 2 + 1) * 8 + chunk) * 16384;
    *(__nv_bfloat16*)(g_Wt + base_hi + sw) = hi;
    *(__nv_bfloat16*)(g_Wt + base_lo + sw) = lo;
    if (k == 0) g_bp[lev * 128 + n] = b[head * DC + jj];
}

// ---------------- 2b) pack W fp32 [512 x 128] per level (fallback) --------
__global__ void pack_W_kernel(const float* __restrict__ W) {
    int idx = blockIdx.x * blockDim.x + threadIdx.x;
    if (idx >= 3 * 512 * 128) return;
    int lev = idx / (512 * 128);
    int rem = idx - lev * (512 * 128);
    int k = rem >> 7;
    int j = rem & 127;
    int head = lev * 2 + (j >> 6);
    int jj = j & 63;
    g_Wp[idx] = (k < FINC) ? W[((size_t)head * FINC + k) * DC + jj] : 0.f;
}

// ---------------- 3) feature GEMM + fused p2 epilogue (R9/R11 config) ------
#define MTILES  4
#define SM_A    0
#define SM_B    65536
#define SM_BITS 98304
#define SM_IDS  131072
#define SM_BIAS 137216
#define SM_A2W  137728
#define SM_A2B  138240
#define SM_LUT  138256
#define SM_PTR  138384
#define SM_MBAR 138392
#define SMEM_TOTAL 138496
#define TMEM_COLS 512

__global__ void __launch_bounds__(256) __cluster_dims__(1, 1, 1)
mma_feat_kernel(int lev, int mode, int n, const int* __restrict__ elem,
                float* __restrict__ out,
                const float* __restrict__ a2w, const float* __restrict__ a2b) {
    extern __shared__ char smem[];
    int t = threadIdx.x;
    int tile0 = blockIdx.x * (128 * MTILES);

    {
        int* ids = (int*)(smem + SM_IDS);
        for (int i = t; i < 128 * MTILES; i += 256) {
            int gr = tile0 + i; if (gr >= n) gr = n - 1;
            int a, bb, c;
            if (mode == 0)      { a = gr; bb = gr; c = gr; }
            else if (mode == 1) { a = elem[2 * gr]; bb = elem[2 * gr + 1]; c = a; }
            else                { a = elem[3 * gr]; bb = elem[3 * gr + 1]; c = elem[3 * gr + 2]; }
            ids[i * 3] = a; ids[i * 3 + 1] = bb; ids[i * 3 + 2] = c;
        }
    }
    if (t < 128) {
        ((float*)(smem + SM_BIAS))[t] = g_bp[lev * 128 + t];
        ((float*)(smem + SM_A2W))[t] = a2w[(lev * 2 + (t >> 6)) * 64 + (t & 63)];
    }
    if (t < 2) ((float*)(smem + SM_A2B))[t] = a2b[lev * 2 + t];
    __syncthreads();
    {
        const int* ids = (const int*)(smem + SM_IDS);
        unsigned* sbits = (unsigned*)(smem + SM_BITS);
        for (int i = t; i < 128 * MTILES * 16; i += 256) {
            int row = i >> 4, w = i & 15;
            unsigned v = g_bits[ids[row * 3] * 16 + w];
            if (mode >= 1) v &= g_bits[ids[row * 3 + 1] * 16 + w];
            if (mode == 2) v &= g_bits[ids[row * 3 + 2] * 16 + w];
            sbits[i] = v;
        }
    }

#if HAS_TC
    uint32_t sb = smem_u32(smem);
    int wid = t >> 5;
    int lane = t & 31;
    if (wid == 0) {
        TC_ALLOC(sb + SM_PTR, TMEM_COLS);
    }
    if (t == 0) MBAR_INIT(sb + SM_MBAR, 1);
    if (t < 16) {
        unsigned w0 = ((t & 1) ? 0x3f80u : 0u) | ((t & 2) ? 0x3f800000u : 0u);
        unsigned w1 = ((t & 4) ? 0x3f80u : 0u) | ((t & 8) ? 0x3f800000u : 0u);
        ((uint2*)(smem + SM_LUT))[t] = make_uint2(w0, w1);
    }
    __syncthreads();

    uint32_t tmem;
    asm volatile("ld.shared.b32 %0, [%1];" : "=r"(tmem) : "r"(sb + SM_PTR));

    const uint2* lut = (const uint2*)(smem + SM_LUT);
    const unsigned* sbits = (const unsigned*)(smem + SM_BITS);
    int arow = t >> 1, ahalf = t & 1;
    const unsigned char* wt = g_Wt + (size_t)lev * (2 * 8 * 16384);

    for (int c = 0; c < 8; c++) {
#pragma unroll
        for (int tile = 0; tile < MTILES; tile++) {
            unsigned bw = sbits[(tile * 128 + arow) * 16 + 2 * c + ahalf];
            char* Abuf = smem + SM_A + tile * 16384;
#pragma unroll
            for (int j = 0; j < 4; j++) {
                unsigned nib0 = (bw >> (j * 8)) & 15u;
                unsigned nib1 = (bw >> (j * 8 + 4)) & 15u;
                uint2 p0 = lut[nib0];
                uint2 p1 = lut[nib1];
                unsigned off = arow * 128 + ahalf * 64 + j * 16;
                unsigned sw = off ^ ((off >> 3) & 0x70);
                *(uint4*)(Abuf + sw) = make_uint4(p0.x, p0.y, p1.x, p1.y);
            }
        }
        {
            const uint4* srcHi = (const uint4*)(wt + (size_t)c * 16384);
            const uint4* srcLo = (const uint4*)(wt + (size_t)(8 + c) * 16384);
            uint4* dstB = (uint4*)(smem + SM_B);
#pragma unroll
            for (int q = 0; q < 4; q++) dstB[q * 256 + t] = srcHi[q * 256 + t];
#pragma unroll
            for (int q = 0; q < 4; q++) dstB[1024 + q * 256 + t] = srcLo[q * 256 + t];
        }
        FENCE_ASYNC();
        __syncthreads();

        if (wid == 0 && elect_one()) {
            uint64_t bdescH = MAKE_DESC(sb + SM_B);
            uint64_t bdescL = MAKE_DESC(sb + SM_B + 16384);
#pragma unroll
            for (int tile = 0; tile < MTILES; tile++) {
                uint64_t adesc = MAKE_DESC(sb + SM_A + tile * 16384);
                uint32_t dbase = tmem + tile * 128;
#pragma unroll
                for (int ks = 0; ks < 4; ks++) {
                    bool first = (c == 0 && ks == 0);
#pragma unroll
                    for (int h = 0; h < 2; h++) {
                        mma_f16_ss(dbase + h * 64, adesc + ks * 2,
                                   bdescH + h * 512 + ks * 2, !first);
                        mma_f16_ss(dbase + h * 64, adesc + ks * 2,
                                   bdescL + h * 512 + ks * 2, true);
                    }
                }
            }
            TC_COMMIT(sb + SM_MBAR);
        }
        MBAR_WAIT(sb + SM_MBAR, c & 1);
        __syncthreads();
    }

    TC_FENCE_AFTER();

    {
        int part = wid & 3, colg = wid >> 2;
        const float* bias = (const float*)(smem + SM_BIAS) + colg * 64;
        const float* sa2w = (const float*)(smem + SM_A2W) + colg * 64;
        float a2bv = ((const float*)(smem + SM_A2B))[colg];
#pragma unroll
        for (int tile = 0; tile < MTILES; tile++) {
            uint32_t d0[32], d1[32];
            TC_LD_X32(d0, tmem + tile * 128 + colg * 64);
            TC_LD_X32(d1, tmem + tile * 128 + colg * 64 + 32);
            TC_WAIT_LD();
            TC_FENCE_BEFORE();
            int gr = tile0 + tile * 128 + part * 32 + lane;
            if (gr < n) {
                float* o = out + (size_t)gr * 128 + colg * 64;
                float s2 = 0.f;
#pragma unroll
                for (int j = 0; j < 8; j++) {
                    float4 v;
                    v.x = __uint_as_float(d0[j * 4 + 0]) + bias[j * 4 + 0];
                    v.y = __uint_as_float(d0[j * 4 + 1]) + bias[j * 4 + 1];
                    v.z = __uint_as_float(d0[j * 4 + 2]) + bias[j * 4 + 2];
                    v.w = __uint_as_float(d0[j * 4 + 3]) + bias[j * 4 + 3];
                    s2 = fmaf(v.x, sa2w[j * 4 + 0], s2);
                    s2 = fmaf(v.y, sa2w[j * 4 + 1], s2);
                    s2 = fmaf(v.z, sa2w[j * 4 + 2], s2);
                    s2 = fmaf(v.w, sa2w[j * 4 + 3], s2);
                    *(float4*)(o + j * 4) = v;
                }
#pragma unroll
                for (int j = 0; j < 8; j++) {
                    float4 v;
                    v.x = __uint_as_float(d1[j * 4 + 0]) + bias[32 + j * 4 + 0];
                    v.y = __uint_as_float(d1[j * 4 + 1]) + bias[32 + j * 4 + 1];
                    v.z = __uint_as_float(d1[j * 4 + 2]) + bias[32 + j * 4 + 2];
                    v.w = __uint_as_float(d1[j * 4 + 3]) + bias[32 + j * 4 + 3];
                    s2 = fmaf(v.x, sa2w[32 + j * 4 + 0], s2);
                    s2 = fmaf(v.y, sa2w[32 + j * 4 + 1], s2);
                    s2 = fmaf(v.z, sa2w[32 + j * 4 + 2], s2);
                    s2 = fmaf(v.w, sa2w[32 + j * 4 + 3], s2);
                    *(float4*)(o + 32 + j * 4) = v;
                }
                g_p2[(lev * 2 + colg) * N1C + gr] = expf(s2 + a2bv);
            }
        }
    }
    __syncthreads();
    if (wid == 0) TC_DEALLOC(tmem, TMEM_COLS);

#else  // ---------------- SIMT fallback (non-sm_103a pass; dead on GB300) --
    const float* Wp = g_Wp + (size_t)lev * 512 * 128;
    float* sW = (float*)(smem + SM_A);
    const unsigned* sbits = (const unsigned*)(smem + SM_BITS);
    int tr = t >> 4, tc = t & 15;
    for (int tile = 0; tile < MTILES; tile++) {
        for (int h = 0; h < 2; h++) {
            float acc[4][8];
#pragma unroll
            for (int i = 0; i < 4; i++)
#pragma unroll
                for (int c = 0; c < 8; c++) acc[i][c] = 0.f;
            for (int w = 0; w < 16; w++) {
                __syncthreads();
                const float4* src = (const float4*)(Wp + (size_t)w * 4096);
                float4* dst = (float4*)sW;
#pragma unroll
                for (int q = 0; q < 4; q++) dst[q * 256 + t] = src[q * 256 + t];
                __syncthreads();
                unsigned a[4];
#pragma unroll
                for (int i = 0; i < 4; i++)
                    a[i] = sbits[(tile * 128 + h * 64 + tr + i * 16) * 16 + w];
                const float4* sv = (const float4*)sW;
#pragma unroll
                for (int kk = 0; kk < 32; kk++) {
                    float4 w0 = sv[kk * 32 + tc * 2];
                    float4 w1 = sv[kk * 32 + tc * 2 + 1];
#pragma unroll
                    for (int i = 0; i < 4; i++) {
                        unsigned msk = (unsigned)(-(int)((a[i] >> kk) & 1u));
                        float av = __uint_as_float(0x3f800000u & msk);
                        acc[i][0] = fmaf(av, w0.x, acc[i][0]);
                        acc[i][1] = fmaf(av, w0.y, acc[i][1]);
                        acc[i][2] = fmaf(av, w0.z, acc[i][2]);
                        acc[i][3] = fmaf(av, w0.w, acc[i][3]);
                        acc[i][4] = fmaf(av, w1.x, acc[i][4]);
                        acc[i][5] = fmaf(av, w1.y, acc[i][5]);
                        acc[i][6] = fmaf(av, w1.z, acc[i][6]);
                        acc[i][7] = fmaf(av, w1.w, acc[i][7]);
                    }
                }
            }
            const float* bias = (const float*)(smem + SM_BIAS) + tc * 8;
#pragma unroll
            for (int i = 0; i < 4; i++) {
                int r = tile0 + tile * 128 + h * 64 + tr + i * 16;
                if (r < n) {
                    float* o = out + (size_t)r * 128 + tc * 8;
#pragma unroll
                    for (int c = 0; c < 8; c++) o[c] = acc[i][c] + bias[c];
                }
            }
        }
    }
#endif
}

// ---------------- 4) z pass: z[r] += p2[c] over COO rows -------------------
__global__ void z_kernel(const int* __restrict__ idx, int nnz, int hA, int hB) {
    int j = blockIdx.x * blockDim.x + threadIdx.x;
    if (j >= nnz) return;
    int r = idx[j], c = idx[nnz + j];
    atomicAdd(&g_z[hA * N1C + r], g_p2[hA * N1C + c]);
    if (hB >= 0) atomicAdd(&g_z[hB * N1C + r], g_p2[hB * N1C + c]);
}

// ---------------- 5) dual-head direct-normalized scatter (shared idx) ------
__global__ void att_scatter2_kernel(const int* __restrict__ idx, int nnz, int hA, int hB,
                                    const float* __restrict__ Xh, float* __restrict__ H) {
    int warp = (blockIdx.x * blockDim.x + threadIdx.x) >> 5;
    int lane = threadIdx.x & 31;
    int j = warp * 2 + (lane >> 4);
    int l = lane & 15;
    if (j >= nnz) return;
    int r = idx[j], c = idx[nnz + j];
    float wA = __fdividef(g_p2[hA * N1C + c], g_z[hA * N1C + r]);
    float wB = __fdividef(g_p2[hB * N1C + c], g_z[hB * N1C + r]);
    float4 hA4 = *(const float4*)(Xh + (size_t)c * 128 + l * 4);
    float4 hB4 = *(const float4*)(Xh + (size_t)c * 128 + 64 + l * 4);
    float4 v;
    v.x = wA * hA4.x + wB * hB4.x;
    v.y = wA * hA4.y + wB * hB4.y;
    v.z = wA * hA4.z + wB * hB4.z;
    v.w = wA * hA4.w + wB * hB4.w;
    atomicAdd((float4*)(H + (size_t)r * 64 + l * 4), v);
}

// ---------------- 6) single-head direct-normalized scatter -----------------
__global__ void att_scatter1_kernel(const int* __restrict__ idx, int nnz, int head,
                                    const float* __restrict__ Xh, float* __restrict__ H) {
    int warp = (blockIdx.x * blockDim.x + threadIdx.x) >> 5;
    int lane = threadIdx.x & 31;
    int j = warp * 2 + (lane >> 4);
    int l = lane & 15;
    if (j >= nnz) return;
    int r = idx[j], c = idx[nnz + j];
    float w = __fdividef(g_p2[head * N1C + c], g_z[head * N1C + r]);
    int hoff = (head & 1) * 64;
    float4 hv = *(const float4*)(Xh + (size_t)c * 128 + hoff + l * 4);
    float4 v; v.x = w * hv.x; v.y = w * hv.y; v.z = w * hv.z; v.w = w * hv.w;
    atomicAdd((float4*)(H + (size_t)r * 64 + l * 4), v);
}

// ---------------- 7) COO spmm with fused PReLU on src ----------------------
__global__ void spmm_kernel(const int* __restrict__ idx, const float* __restrict__ vals,
                            int nnz, const float* __restrict__ src, float* __restrict__ dst,
                            const float* __restrict__ pw) {
    int warp = (blockIdx.x * blockDim.x + threadIdx.x) >> 5;
    int lane = threadIdx.x & 31;
    int j = warp * 2 + (lane >> 4);
    int l = lane & 15;
    if (j >= nnz) return;
    int r = idx[j], c = idx[nnz + j];
    float val = vals[j];
    float p = pw[0];
    float4 x = *(const float4*)(src + (size_t)c * 64 + l * 4);
    x.x = (x.x >= 0.f) ? x.x : p * x.x;
    x.y = (x.y >= 0.f) ? x.y : p * x.y;
    x.z = (x.z >= 0.f) ? x.z : p * x.z;
    x.w = (x.w >= 0.f) ? x.w : p * x.w;
    float4 v; v.x = val * x.x; v.y = val * x.y; v.z = val * x.z; v.w = val * x.w;
    atomicAdd((float4*)(dst + (size_t)r * 64 + l * 4), v);
}

// ---------------- 7b) tsum: rowsum of B1 values (no computed inputs) -------
__global__ void tsum_kernel(const int* __restrict__ idx, const float* __restrict__ vals,
                            int nnz) {
    int j = blockIdx.x * blockDim.x + threadIdx.x;
    if (j >= nnz) return;
    atomicAdd(&g_tsum[idx[j]], vals[j]);
}

// ---------------- 8) fused B1 spmm: S1 += val*prelu(H1[c]); V += val*U[c] --
__global__ void spmm_b1_fused_kernel(const int* __restrict__ idx, const float* __restrict__ vals,
                                     int nnz, const float* __restrict__ pw) {
    int warp = (blockIdx.x * blockDim.x + threadIdx.x) >> 5;
    int lane = threadIdx.x & 31;
    int j = warp * 2 + (lane >> 4);
    int l = lane & 15;
    if (j >= nnz) return;
    int r = idx[j], c = idx[nnz + j];
    float val = vals[j];
    float p = pw[0];
    float4 x1 = *(const float4*)(g_H1 + (size_t)c * 64 + l * 4);
    x1.x = (x1.x >= 0.f) ? x1.x : p * x1.x;
    x1.y = (x1.y >= 0.f) ? x1.y : p * x1.y;
    x1.z = (x1.z >= 0.f) ? x1.z : p * x1.z;
    x1.w = (x1.w >= 0.f) ? x1.w : p * x1.w;
    float4 xu = *(const float4*)(g_U  + (size_t)c * 64 + l * 4);
    float4 v1; v1.x = val * x1.x; v1.y = val * x1.y; v1.z = val * x1.z; v1.w = val * x1.w;
    float4 vu; vu.x = val * xu.x; vu.y = val * xu.y; vu.z = val * xu.z; vu.w = val * xu.w;
    atomicAdd((float4*)(g_S1 + (size_t)r * 64 + l * 4), v1);
    atomicAdd((float4*)(g_V  + (size_t)r * 64 + l * 4), vu);
}

// ---------------- 9) final: out = (prelu(H0) + S1 + V@triW + tsum*trib)/3 --
__global__ void __launch_bounds__(256)
final_kernel(const float* __restrict__ triW, const float* __restrict__ trib,
             float* __restrict__ out, int n0, const float* __restrict__ pw) {
    __shared__ float sT[64 * 64];
    int t = threadIdx.x;
#pragma unroll
    for (int q = 0; q < 16; q++) sT[q * 256 + t] = triW[q * 256 + t];
    __syncthreads();
    int gw = blockIdx.x * 8 + (t >> 5);
    int lane = t & 31;
    if (gw >= n0) return;
    float p = pw[0];
    float2 v = *(const float2*)(g_V + (size_t)gw * 64 + lane * 2);
    float2 o; o.x = 0.f; o.y = 0.f;
#pragma unroll
    for (int k = 0; k < 64; k++) {
        float vk = __shfl_sync(0xffffffffu, (k & 1) ? v.y : v.x, k >> 1);
        float2 tw = *(const float2*)(sT + k * 64 + lane * 2);
        o.x = fmaf(vk, tw.x, o.x);
        o.y = fmaf(vk, tw.y, o.y);
    }
    float2 h0 = *(const float2*)(g_H0 + (size_t)gw * 64 + lane * 2);
    h0.x = (h0.x >= 0.f) ? h0.x : p * h0.x;
    h0.y = (h0.y >= 0.f) ? h0.y : p * h0.y;
    float2 s1 = *(const float2*)(g_S1 + (size_t)gw * 64 + lane * 2);
    float ts = g_tsum[gw];
    float2 tb = *(const float2*)(trib + lane * 2);
    float2 r;
    r.x = (h0.x + s1.x + o.x + ts * tb.x) * (1.f / 3.f);
    r.y = (h0.y + s1.y + o.y + ts * tb.y) * (1.f / 3.f);
    *(float2*)(out + (size_t)gw * 64 + lane * 2) = r;
}

// ======================== host launcher ====================================
static inline void* symaddr(const void* sym) {
    void* p = nullptr;
    cudaGetSymbolAddress(&p, sym);
    return p;
}

extern "C" void kernel_launch(void* const* d_in, const int* in_sizes, int n_in,
                              void* d_out, int out_size) {
    const float* X0  = (const float*)d_in[0];
    const int*   E1  = (const int*)d_in[1];
    const int*   T2  = (const int*)d_in[2];
    const int*   L0  = (const int*)d_in[3];
    const int*   L1a = (const int*)d_in[4];
    const int*   L1b = (const int*)d_in[5];
    const int*   L2  = (const int*)d_in[6];
    const int*   B1i = (const int*)d_in[7];
    const float* B1v = (const float*)d_in[8];
    const int*   B2i = (const int*)d_in[9];
    const float* B2v = (const float*)d_in[10];
    const float* W   = (const float*)d_in[11];
    const float* b   = (const float*)d_in[12];
    const float* a2w = (const float*)d_in[15];
    const float* a2b = (const float*)d_in[16];
    const float* pw  = (const float*)d_in[17];
    const float* triW = (const float*)d_in[18];
    const float* trib = (const float*)d_in[19];

    int n0 = in_sizes[0] / FINC;
    int n1 = in_sizes[1] / 2;
    int n2 = in_sizes[2] / 3;
    int nnz0  = in_sizes[3] / 2;
    int nnz1a = in_sizes[4] / 2;
    int nnz1b = in_sizes[5] / 2;
    int nnz2  = in_sizes[6] / 2;
    int nb1 = in_sizes[8];
    int nb2 = in_sizes[10];

    float* Xh0 = (float*)symaddr(g_Xh0);
    float* Xh1 = (float*)symaddr(g_Xh1);
    float* Xh2 = (float*)symaddr(g_Xh2);
    float* H0  = (float*)symaddr(g_H0);
    float* H1  = (float*)symaddr(g_H1);
    float* H2  = (float*)symaddr(g_H2);
    float* S1  = (float*)symaddr(g_S1);
    float* U   = (float*)symaddr(g_U);
    float* V   = (float*)symaddr(g_V);
    float* tsum = (float*)symaddr(g_tsum);
    float* z   = (float*)symaddr(g_z);

    // one-time setup (first call is the uncaptured correctness run)
    static cudaStream_t sA = nullptr, sB = nullptr, sC = nullptr;
    static cudaEvent_t evStart = nullptr, evFork = nullptr, evG1 = nullptr;
    static cudaEvent_t evA = nullptr, evB = nullptr, evC = nullptr;
    static bool init_done = false;
    if (!init_done) {
        cudaFuncSetAttribute(mma_feat_kernel,
                             cudaFuncAttributeMaxDynamicSharedMemorySize, SMEM_TOTAL);
        cudaStreamCreateWithFlags(&sA, cudaStreamNonBlocking);
        cudaStreamCreateWithFlags(&sB, cudaStreamNonBlocking);
        cudaStreamCreateWithFlags(&sC, cudaStreamNonBlocking);
        cudaEventCreateWithFlags(&evStart, cudaEventDisableTiming);
        cudaEventCreateWithFlags(&evFork, cudaEventDisableTiming);
        cudaEventCreateWithFlags(&evG1, cudaEventDisableTiming);
        cudaEventCreateWithFlags(&evA, cudaEventDisableTiming);
        cudaEventCreateWithFlags(&evB, cudaEventDisableTiming);
        cudaEventCreateWithFlags(&evC, cudaEventDisableTiming);
        init_done = true;
    }

    // ---- immediate fork so per-stream memsets overlap the packs ----
    cudaEventRecord(evStart, 0);
    cudaStreamWaitEvent(sB, evStart, 0);
    cudaStreamWaitEvent(sC, evStart, 0);
    cudaStreamWaitEvent(sA, evStart, 0);

    // per-stream buffer zeroing (off the pack critical path)
    // sB: level-1 buffers (both heads; head-3 consumer on sA orders via evG1)
    cudaMemsetAsync(H1, 0, sizeof(float) * (size_t)n1 * 64, sB);
    cudaMemsetAsync(z + 2 * N1C, 0, sizeof(float) * 2 * N1C, sB);      // heads 2,3
    // sC: level-2 buffers
    cudaMemsetAsync(H2, 0, sizeof(float) * (size_t)n2 * 64, sC);
    cudaMemsetAsync(U,  0, sizeof(float) * (size_t)n1 * 64, sC);
    cudaMemsetAsync(z + 4 * N1C, 0, sizeof(float) * 2 * N1C, sC);      // heads 4,5
    // sA: level-0 buffers + join-phase buffers + early tsum + fallback pack
    cudaMemsetAsync(H0, 0, sizeof(float) * (size_t)n0 * 64, sA);
    cudaMemsetAsync(z,  0, sizeof(float) * 2 * N1C, sA);               // heads 0,1
    cudaMemsetAsync(S1, 0, sizeof(float) * (size_t)n0 * 64, sA);
    cudaMemsetAsync(V,  0, sizeof(float) * (size_t)n0 * 64, sA);
    cudaMemsetAsync(tsum, 0, sizeof(float) * (size_t)n0, sA);
    tsum_kernel<<<(nb1 + 255) / 256, 256, 0, sA>>>(B1i, B1v, nb1);     // needs only B1 inputs
    pack_W_kernel<<<(3 * 512 * 128 + 255) / 256, 256, 0, sA>>>(W);     // fallback-only

    // ---- packs on the capture stream (GEMM prerequisites) ----
    pack_bits_kernel<<<(n0 * 32 + 255) / 256, 256>>>(X0, n0);
    pack_Wt_kernel<<<(3 * 8 * 128 * 64 + 255) / 256, 256>>>(W, b);
    cudaEventRecord(evFork, 0);
    cudaStreamWaitEvent(sB, evFork, 0);
    cudaStreamWaitEvent(sC, evFork, 0);
    cudaStreamWaitEvent(sA, evFork, 0);

    // level 1 (edges) FIRST on stream B: gates the longest chain
    mma_feat_kernel<<<(n1 + 511) / 512, 256, SMEM_TOTAL, sB>>>(1, 1, n1, E1, Xh1, a2w, a2b);
    cudaEventRecord(evG1, sB);
    z_kernel<<<(nnz1a + 255) / 256, 256, 0, sB>>>(L1a, nnz1a, 2, -1);
    att_scatter1_kernel<<<(nnz1a + 15) / 16, 256, 0, sB>>>(L1a, nnz1a, 2, Xh1, H1);
    cudaEventRecord(evB, sB);

    // level 2 (triangles) on stream C, then the B2 spmm which needs only H2
    mma_feat_kernel<<<(n2 + 511) / 512, 256, SMEM_TOTAL, sC>>>(2, 2, n2, T2, Xh2, a2w, a2b);
    z_kernel<<<(nnz2 + 255) / 256, 256, 0, sC>>>(L2, nnz2, 4, 5);
    att_scatter2_kernel<<<(nnz2 + 15) / 16, 256, 0, sC>>>(L2, nnz2, 4, 5, Xh2, H2);
    spmm_kernel<<<(nb2 + 15) / 16, 256, 0, sC>>>(B2i, B2v, nb2, H2, U, pw);
    cudaEventRecord(evC, sC);

    // level 0 (nodes) on stream A, then the head-3 chain once GEMM1 is done
    mma_feat_kernel<<<(n0 + 511) / 512, 256, SMEM_TOTAL, sA>>>(0, 0, n0, E1, Xh0, a2w, a2b);
    z_kernel<<<(nnz0 + 255) / 256, 256, 0, sA>>>(L0, nnz0, 0, 1);
    att_scatter2_kernel<<<(nnz0 + 15) / 16, 256, 0, sA>>>(L0, nnz0, 0, 1, Xh0, H0);
    cudaStreamWaitEvent(sA, evG1, 0);
    z_kernel<<<(nnz1b + 255) / 256, 256, 0, sA>>>(L1b, nnz1b, 3, -1);
    att_scatter1_kernel<<<(nnz1b + 15) / 16, 256, 0, sA>>>(L1b, nnz1b, 3, Xh1, H1);
    cudaEventRecord(evA, sA);

    // ---- join on the capture stream ----
    cudaStreamWaitEvent(0, evB, 0);
    cudaStreamWaitEvent(0, evC, 0);
    cudaStreamWaitEvent(0, evA, 0);

    // B1 spmm (needs H1, U; tsum already done) then final combine
    spmm_b1_fused_kernel<<<(nb1 + 15) / 16, 256>>>(B1i, B1v, nb1, pw);
    final_kernel<<<(n0 + 7) / 8, 256>>>(triW, trib, (float*)d_out, n0, pw);
}